// round 1
// baseline (speedup 1.0000x reference)
#include <cuda_runtime.h>

#define N_NODES 50000
#define N_EDGES 800000
#define DIM     256
#define DIM4    64          // DIM/4

// ---------------- scratch (device globals: allocation-free rule) ----------
__device__ int   g_idx64;                      // 1 if indices are int64
__device__ float g_norm_s[N_NODES];            // also used as out-degree accum
__device__ float g_norm_d[N_NODES];            // also used as in-degree accum
__device__ float g_hs [(size_t)N_NODES * DIM]; // h * norm_s (gather source)
__device__ float g_agg[(size_t)N_NODES * DIM]; // segment-sum accumulator
__device__ float g_h1 [(size_t)N_NODES * DIM]; // layer-1 output

// ---------------- index dtype sniffing ------------------------------------
// jax randint(dtype=int64) collapses to int32 unless x64 is enabled; we can't
// tell from in_sizes. Values are < 50000 < 2^31, so if the array is int64 every
// odd 32-bit word is zero. Probability of 4096 random int32 indices all being
// zero is ~0, so this is a safe discriminator.
__global__ void detect_kernel(const int* __restrict__ src_w) {
    __shared__ int any;
    if (threadIdx.x == 0) any = 0;
    __syncthreads();
    for (int i = threadIdx.x; i < 4096; i += blockDim.x)
        if (src_w[2 * i + 1] != 0) any = 1;   // benign race (same value)
    __syncthreads();
    if (threadIdx.x == 0) g_idx64 = (any == 0) ? 1 : 0;
}

__device__ __forceinline__ int load_idx(const void* p, int i, int is64) {
    return is64 ? (int)((const long long*)p)[i] : ((const int*)p)[i];
}

// ---------------- small utility kernels -----------------------------------
__global__ void zero_norms_kernel() {
    int i = blockIdx.x * blockDim.x + threadIdx.x;
    if (i < N_NODES) { g_norm_s[i] = 0.f; g_norm_d[i] = 0.f; }
}

__global__ void zero_agg_kernel() {            // N_NODES*DIM/4 threads exactly
    int i = blockIdx.x * blockDim.x + threadIdx.x;
    ((float4*)g_agg)[i] = make_float4(0.f, 0.f, 0.f, 0.f);
}

__global__ void zero_hg_kernel(float* __restrict__ hg) {
    int i = blockIdx.x * blockDim.x + threadIdx.x;
    if (i < 2 * DIM) hg[i] = 0.f;
}

__global__ void degree_kernel(const void* __restrict__ src,
                              const void* __restrict__ dst) {
    int e = blockIdx.x * blockDim.x + threadIdx.x;
    if (e >= N_EDGES) return;
    int is64 = g_idx64;
    atomicAdd(&g_norm_s[load_idx(src, e, is64)], 1.f);
    atomicAdd(&g_norm_d[load_idx(dst, e, is64)], 1.f);
}

__global__ void norm_kernel() {
    int i = blockIdx.x * blockDim.x + threadIdx.x;
    if (i >= N_NODES) return;
    g_norm_s[i] = rsqrtf(fmaxf(g_norm_s[i], 1.f));
    g_norm_d[i] = rsqrtf(fmaxf(g_norm_d[i], 1.f));
}

// hs = h * norm_s  (vectorized; N_NODES*DIM4 threads exactly)
__global__ void scale_rows_kernel(const float4* __restrict__ h,
                                  float4* __restrict__ hs) {
    int i = blockIdx.x * blockDim.x + threadIdx.x;   // < N_NODES*64
    float ns = g_norm_s[i >> 6];
    float4 v = h[i];
    v.x *= ns; v.y *= ns; v.z *= ns; v.w *= ns;
    hs[i] = v;
}

// Edge scatter: one thread per (edge, float4-chunk). Warp covers 512
// consecutive bytes of one row -> fully coalesced gather; scatter via
// vector reduction (red.global.add.v4.f32, sm_90+), 1 L2 atomic per 16B.
__global__ void scatter_kernel(const void* __restrict__ src,
                               const void* __restrict__ dst) {
    long long t = (long long)blockIdx.x * blockDim.x + threadIdx.x;
    int e = (int)(t >> 6);
    int c = (int)(t & 63);
    int is64 = g_idx64;
    int s = load_idx(src, e, is64);
    int d = load_idx(dst, e, is64);
    float4 v = ((const float4*)g_hs)[(size_t)s * DIM4 + c];
    float4* p = (float4*)g_agg + (size_t)d * DIM4 + c;
    asm volatile("red.global.add.v4.f32 [%0], {%1,%2,%3,%4};"
                 :: "l"(p), "f"(v.x), "f"(v.y), "f"(v.z), "f"(v.w)
                 : "memory");
}

// ---------------- GEMM: out = prelu((A .* norm_d) @ W + b) -----------------
// A: [M,256] row-major, W: [256,256] row-major. 128x128 tile, BK=16,
// 256 threads, 8x8 microtile per thread.
__global__ __launch_bounds__(256)
void gemm_prelu_kernel(const float* __restrict__ A,
                       const float* __restrict__ normd,
                       const float* __restrict__ W,
                       const float* __restrict__ bias,
                       const float* __restrict__ prelu_a,
                       float* __restrict__ out, int M) {
    __shared__ float As[16][128];
    __shared__ float Bs[16][128];
    const int bm = blockIdx.x * 128;
    const int bn = blockIdx.y * 128;
    const int tid = threadIdx.x;
    const int tx = tid & 15;        // 16 cols of threads
    const int ty = tid >> 4;        // 16 rows of threads

    float acc[8][8];
#pragma unroll
    for (int i = 0; i < 8; i++)
#pragma unroll
        for (int j = 0; j < 8; j++) acc[i][j] = 0.f;

    for (int k0 = 0; k0 < DIM; k0 += 16) {
#pragma unroll
        for (int l = 0; l < 2; l++) {
            int idx = tid + l * 256;
            // A tile: 128 rows x 16 cols = 512 float4; row-major gmem read,
            // transposed smem store; fuse norm_d scaling here.
            int row = idx >> 2, c4 = idx & 3;
            float4 v = make_float4(0.f, 0.f, 0.f, 0.f);
            int gr = bm + row;
            if (gr < M) {
                v = *(const float4*)(A + (size_t)gr * DIM + k0 + c4 * 4);
                float nd = normd[gr];
                v.x *= nd; v.y *= nd; v.z *= nd; v.w *= nd;
            }
            As[c4 * 4 + 0][row] = v.x;
            As[c4 * 4 + 1][row] = v.y;
            As[c4 * 4 + 2][row] = v.z;
            As[c4 * 4 + 3][row] = v.w;
            // B tile: 16 rows x 128 cols = 512 float4, direct layout.
            int kk = idx >> 5, n4 = idx & 31;
            float4 w4 = *(const float4*)(W + (size_t)(k0 + kk) * DIM + bn + n4 * 4);
            *(float4*)&Bs[kk][n4 * 4] = w4;
        }
        __syncthreads();
#pragma unroll
        for (int k = 0; k < 16; k++) {
            float a[8], b[8];
#pragma unroll
            for (int i = 0; i < 2; i++)
                *(float4*)&a[i * 4] = *(const float4*)&As[k][ty * 8 + i * 4];
#pragma unroll
            for (int j = 0; j < 2; j++)
                *(float4*)&b[j * 4] = *(const float4*)&Bs[k][tx * 8 + j * 4];
#pragma unroll
            for (int i = 0; i < 8; i++)
#pragma unroll
                for (int j = 0; j < 8; j++)
                    acc[i][j] += a[i] * b[j];
        }
        __syncthreads();
    }

    const float pa = __ldg(prelu_a);
#pragma unroll
    for (int i = 0; i < 8; i++) {
        int gr = bm + ty * 8 + i;
        if (gr >= M) continue;
#pragma unroll
        for (int j = 0; j < 2; j++) {
            int gc = bn + tx * 8 + j * 4;
            float4 r;
            r.x = acc[i][j * 4 + 0] + bias[gc + 0];
            r.y = acc[i][j * 4 + 1] + bias[gc + 1];
            r.z = acc[i][j * 4 + 2] + bias[gc + 2];
            r.w = acc[i][j * 4 + 3] + bias[gc + 3];
            r.x = (r.x >= 0.f) ? r.x : pa * r.x;
            r.y = (r.y >= 0.f) ? r.y : pa * r.y;
            r.z = (r.z >= 0.f) ? r.z : pa * r.z;
            r.w = (r.w >= 0.f) ? r.w : pa * r.w;
            *(float4*)(out + (size_t)gr * DIM + gc) = r;
        }
    }
}

// Column sum (SumPooling readout): block b handles 250 rows, thread c = column.
__global__ void colsum_kernel(const float* __restrict__ h,
                              float* __restrict__ hg) {
    int c = threadIdx.x;
    int r0 = blockIdx.x * 250;
    float s = 0.f;
    for (int r = 0; r < 250; r++)
        s += h[(size_t)(r0 + r) * DIM + c];
    atomicAdd(&hg[c], s);
}

// ---------------- launch ----------------------------------------------------
extern "C" void kernel_launch(void* const* d_in, const int* in_sizes, int n_in,
                              void* d_out, int out_size) {
    const float* feat = (const float*)d_in[0];
    const void*  src  = d_in[1];
    const void*  dst  = d_in[2];
    const float* W0   = (const float*)d_in[3];
    const float* b0   = (const float*)d_in[4];
    const float* W1   = (const float*)d_in[5];
    const float* b1   = (const float*)d_in[6];
    const float* pa   = (const float*)d_in[7];
    float* out = (float*)d_out;
    float* hg  = out + (size_t)N_NODES * DIM;   // [512] readout tail

    float *p_hs, *p_agg, *p_h1, *p_nd;
    cudaGetSymbolAddress((void**)&p_hs,  g_hs);
    cudaGetSymbolAddress((void**)&p_agg, g_agg);
    cudaGetSymbolAddress((void**)&p_h1,  g_h1);
    cudaGetSymbolAddress((void**)&p_nd,  g_norm_d);

    const int TB = 256;
    const int nodeBlk  = (N_NODES + TB - 1) / TB;
    const int edgeBlk  = (N_EDGES + TB - 1) / TB;
    const int rowBlk   = N_NODES * DIM4 / TB;          // 12500, exact
    const long long scatterThreads = (long long)N_EDGES * DIM4;
    const int scatterBlk = (int)(scatterThreads / TB); // 200000, exact
    dim3 gemmGrid((N_NODES + 127) / 128, DIM / 128);

    // ---- degrees & norms ----
    detect_kernel<<<1, 256>>>((const int*)src);
    zero_norms_kernel<<<nodeBlk, TB>>>();
    degree_kernel<<<edgeBlk, TB>>>(src, dst);
    norm_kernel<<<nodeBlk, TB>>>();
    zero_hg_kernel<<<2, TB>>>(hg);

    // ---- layer 1 ----
    scale_rows_kernel<<<rowBlk, TB>>>((const float4*)feat, (float4*)p_hs);
    zero_agg_kernel<<<rowBlk, TB>>>();
    scatter_kernel<<<scatterBlk, TB>>>(src, dst);
    gemm_prelu_kernel<<<gemmGrid, TB>>>(p_agg, p_nd, W0, b0, pa, p_h1, N_NODES);
    colsum_kernel<<<200, TB>>>(p_h1, hg);              // hg[0:256]

    // ---- layer 2 ----
    scale_rows_kernel<<<rowBlk, TB>>>((const float4*)p_h1, (float4*)p_hs);
    zero_agg_kernel<<<rowBlk, TB>>>();
    scatter_kernel<<<scatterBlk, TB>>>(src, dst);
    gemm_prelu_kernel<<<gemmGrid, TB>>>(p_agg, p_nd, W1, b1, pa, out, N_NODES);
    colsum_kernel<<<200, TB>>>(out, hg + DIM);         // hg[256:512]
}

// round 2
// speedup vs baseline: 1.4068x; 1.4068x over previous
#include <cuda_runtime.h>

#define N_NODES 50000
#define N_EDGES 800000
#define DIM     256
#define DIM4    64          // DIM/4

// ---------------- scratch (device globals: allocation-free rule) ----------
__device__ int   g_idx64;                      // 1 if indices are int64
__device__ int   g_deg_out[N_NODES];
__device__ int   g_deg_in [N_NODES];
__device__ float g_norm_s[N_NODES];
__device__ float g_norm_d[N_NODES];
__device__ int   g_row_off[N_NODES + 1];       // CSR offsets (by dst)
__device__ int   g_cursor [N_NODES];           // fill cursors
__device__ int   g_csr_src[N_EDGES];           // src node per CSR slot
__device__ float g_agg[(size_t)N_NODES * DIM]; // segment-sum result
__device__ float g_h1 [(size_t)N_NODES * DIM]; // layer-1 output

// ---------------- index dtype sniffing ------------------------------------
// jax randint(int64) usually materializes as int32 unless x64 is enabled.
// Values < 50000 < 2^31, so for int64 every odd 32-bit word is zero.
__global__ void detect_kernel(const int* __restrict__ src_w) {
    __shared__ int any;
    if (threadIdx.x == 0) any = 0;
    __syncthreads();
    for (int i = threadIdx.x; i < 4096; i += blockDim.x)
        if (src_w[2 * i + 1] != 0) any = 1;   // benign race (same value)
    __syncthreads();
    if (threadIdx.x == 0) g_idx64 = (any == 0) ? 1 : 0;
}

__device__ __forceinline__ int load_idx(const void* p, int i, int is64) {
    return is64 ? (int)((const long long*)p)[i] : ((const int*)p)[i];
}

// ---------------- degrees, norms, CSR --------------------------------------
__global__ void zero_deg_kernel() {
    int i = blockIdx.x * blockDim.x + threadIdx.x;
    if (i < N_NODES) { g_deg_out[i] = 0; g_deg_in[i] = 0; }
}

__global__ void degree_kernel(const void* __restrict__ src,
                              const void* __restrict__ dst) {
    int e = blockIdx.x * blockDim.x + threadIdx.x;
    if (e >= N_EDGES) return;
    int is64 = g_idx64;
    atomicAdd(&g_deg_out[load_idx(src, e, is64)], 1);
    atomicAdd(&g_deg_in [load_idx(dst, e, is64)], 1);
}

__global__ void norm_kernel() {
    int i = blockIdx.x * blockDim.x + threadIdx.x;
    if (i >= N_NODES) return;
    g_norm_s[i] = rsqrtf(fmaxf((float)g_deg_out[i], 1.f));
    g_norm_d[i] = rsqrtf(fmaxf((float)g_deg_in[i],  1.f));
}

// Single-block exclusive scan of g_deg_in -> g_row_off / g_cursor.
__global__ void scan_kernel() {
    __shared__ int sh[1024];
    __shared__ int carry_s;
    if (threadIdx.x == 0) carry_s = 0;
    __syncthreads();
    for (int base = 0; base < N_NODES; base += 1024) {
        int i = base + (int)threadIdx.x;
        int v = (i < N_NODES) ? g_deg_in[i] : 0;
        sh[threadIdx.x] = v;
        __syncthreads();
        for (int off = 1; off < 1024; off <<= 1) {
            int t = (threadIdx.x >= off) ? sh[threadIdx.x - off] : 0;
            __syncthreads();
            sh[threadIdx.x] += t;
            __syncthreads();
        }
        int incl = sh[threadIdx.x];
        int carry = carry_s;
        if (i < N_NODES) {
            int o = carry + incl - v;          // exclusive
            g_row_off[i] = o;
            g_cursor[i]  = o;
        }
        __syncthreads();
        if (threadIdx.x == 1023) carry_s = carry + incl;
        __syncthreads();
    }
    if (threadIdx.x == 0) g_row_off[N_NODES] = carry_s;
}

__global__ void fill_kernel(const void* __restrict__ src,
                            const void* __restrict__ dst) {
    int e = blockIdx.x * blockDim.x + threadIdx.x;
    if (e >= N_EDGES) return;
    int is64 = g_idx64;
    int s = load_idx(src, e, is64);
    int d = load_idx(dst, e, is64);
    int pos = atomicAdd(&g_cursor[d], 1);
    g_csr_src[pos] = s;
}

// ---------------- aggregation: gather-only, atomic-free ---------------------
// warp w -> node d = w>>1, half-row h = w&1. Lane covers one float4 chunk.
// agg[d] = sum_{j in CSR[d]} h[src_j] * norm_s[src_j]   (scale fused here)
__global__ __launch_bounds__(256)
void gather_kernel(const float4* __restrict__ h) {
    int warp = (int)((blockIdx.x * blockDim.x + threadIdx.x) >> 5);
    int lane = threadIdx.x & 31;
    int d    = warp >> 1;
    if (d >= N_NODES) return;
    int chunk = ((warp & 1) << 5) + lane;
    int beg = g_row_off[d];
    int end = g_row_off[d + 1];
    float4 acc = make_float4(0.f, 0.f, 0.f, 0.f);
    for (int j = beg; j < end; j++) {
        int   s  = g_csr_src[j];
        float ns = g_norm_s[s];
        float4 v = h[(size_t)s * DIM4 + chunk];
        acc.x += v.x * ns; acc.y += v.y * ns;
        acc.z += v.z * ns; acc.w += v.w * ns;
    }
    ((float4*)g_agg)[(size_t)d * DIM4 + chunk] = acc;
}

// ---------------- GEMM: out = prelu((A .* norm_d) @ W + b) -----------------
__global__ __launch_bounds__(256)
void gemm_prelu_kernel(const float* __restrict__ A,
                       const float* __restrict__ normd,
                       const float* __restrict__ W,
                       const float* __restrict__ bias,
                       const float* __restrict__ prelu_a,
                       float* __restrict__ out, int M) {
    __shared__ float As[16][128];
    __shared__ float Bs[16][128];
    const int bm = blockIdx.x * 128;
    const int bn = blockIdx.y * 128;
    const int tid = threadIdx.x;
    const int tx = tid & 15;
    const int ty = tid >> 4;

    float acc[8][8];
#pragma unroll
    for (int i = 0; i < 8; i++)
#pragma unroll
        for (int j = 0; j < 8; j++) acc[i][j] = 0.f;

    for (int k0 = 0; k0 < DIM; k0 += 16) {
#pragma unroll
        for (int l = 0; l < 2; l++) {
            int idx = tid + l * 256;
            int row = idx >> 2, c4 = idx & 3;
            float4 v = make_float4(0.f, 0.f, 0.f, 0.f);
            int gr = bm + row;
            if (gr < M) {
                v = *(const float4*)(A + (size_t)gr * DIM + k0 + c4 * 4);
                float nd = normd[gr];
                v.x *= nd; v.y *= nd; v.z *= nd; v.w *= nd;
            }
            As[c4 * 4 + 0][row] = v.x;
            As[c4 * 4 + 1][row] = v.y;
            As[c4 * 4 + 2][row] = v.z;
            As[c4 * 4 + 3][row] = v.w;
            int kk = idx >> 5, n4 = idx & 31;
            float4 w4 = *(const float4*)(W + (size_t)(k0 + kk) * DIM + bn + n4 * 4);
            *(float4*)&Bs[kk][n4 * 4] = w4;
        }
        __syncthreads();
#pragma unroll
        for (int k = 0; k < 16; k++) {
            float a[8], b[8];
#pragma unroll
            for (int i = 0; i < 2; i++)
                *(float4*)&a[i * 4] = *(const float4*)&As[k][ty * 8 + i * 4];
#pragma unroll
            for (int j = 0; j < 2; j++)
                *(float4*)&b[j * 4] = *(const float4*)&Bs[k][tx * 8 + j * 4];
#pragma unroll
            for (int i = 0; i < 8; i++)
#pragma unroll
                for (int j = 0; j < 8; j++)
                    acc[i][j] += a[i] * b[j];
        }
        __syncthreads();
    }

    const float pa = __ldg(prelu_a);
#pragma unroll
    for (int i = 0; i < 8; i++) {
        int gr = bm + ty * 8 + i;
        if (gr >= M) continue;
#pragma unroll
        for (int j = 0; j < 2; j++) {
            int gc = bn + tx * 8 + j * 4;
            float4 r;
            r.x = acc[i][j * 4 + 0] + bias[gc + 0];
            r.y = acc[i][j * 4 + 1] + bias[gc + 1];
            r.z = acc[i][j * 4 + 2] + bias[gc + 2];
            r.w = acc[i][j * 4 + 3] + bias[gc + 3];
            r.x = (r.x >= 0.f) ? r.x : pa * r.x;
            r.y = (r.y >= 0.f) ? r.y : pa * r.y;
            r.z = (r.z >= 0.f) ? r.z : pa * r.z;
            r.w = (r.w >= 0.f) ? r.w : pa * r.w;
            *(float4*)(out + (size_t)gr * DIM + gc) = r;
        }
    }
}

__global__ void zero_hg_kernel(float* __restrict__ hg) {
    int i = blockIdx.x * blockDim.x + threadIdx.x;
    if (i < 2 * DIM) hg[i] = 0.f;
}

// Column sum (SumPooling readout): block b handles 250 rows, thread c = column.
__global__ void colsum_kernel(const float* __restrict__ h,
                              float* __restrict__ hg) {
    int c = threadIdx.x;
    int r0 = blockIdx.x * 250;
    float s = 0.f;
    for (int r = 0; r < 250; r++)
        s += h[(size_t)(r0 + r) * DIM + c];
    atomicAdd(&hg[c], s);
}

// ---------------- launch ----------------------------------------------------
extern "C" void kernel_launch(void* const* d_in, const int* in_sizes, int n_in,
                              void* d_out, int out_size) {
    const float* feat = (const float*)d_in[0];
    const void*  src  = d_in[1];
    const void*  dst  = d_in[2];
    const float* W0   = (const float*)d_in[3];
    const float* b0   = (const float*)d_in[4];
    const float* W1   = (const float*)d_in[5];
    const float* b1   = (const float*)d_in[6];
    const float* pa   = (const float*)d_in[7];
    float* out = (float*)d_out;
    float* hg  = out + (size_t)N_NODES * DIM;   // [512] readout tail

    float *p_agg, *p_h1, *p_nd;
    cudaGetSymbolAddress((void**)&p_agg, g_agg);
    cudaGetSymbolAddress((void**)&p_h1,  g_h1);
    cudaGetSymbolAddress((void**)&p_nd,  g_norm_d);

    const int TB = 256;
    const int nodeBlk = (N_NODES + TB - 1) / TB;
    const int edgeBlk = (N_EDGES + TB - 1) / TB;
    const int gatherBlk = (N_NODES * 2 * 32 + TB - 1) / TB;  // 2 warps/node
    dim3 gemmGrid((N_NODES + 127) / 128, DIM / 128);

    // ---- degrees, norms, CSR (built once, used by both layers) ----
    detect_kernel<<<1, 256>>>((const int*)src);
    zero_deg_kernel<<<nodeBlk, TB>>>();
    degree_kernel<<<edgeBlk, TB>>>(src, dst);
    norm_kernel<<<nodeBlk, TB>>>();
    scan_kernel<<<1, 1024>>>();
    fill_kernel<<<edgeBlk, TB>>>(src, dst);
    zero_hg_kernel<<<2, TB>>>(hg);

    // ---- layer 1 ----
    gather_kernel<<<gatherBlk, TB>>>((const float4*)feat);
    gemm_prelu_kernel<<<gemmGrid, TB>>>(p_agg, p_nd, W0, b0, pa, p_h1, N_NODES);
    colsum_kernel<<<200, TB>>>(p_h1, hg);              // hg[0:256]

    // ---- layer 2 ----
    gather_kernel<<<gatherBlk, TB>>>((const float4*)p_h1);
    gemm_prelu_kernel<<<gemmGrid, TB>>>(p_agg, p_nd, W1, b1, pa, out, N_NODES);
    colsum_kernel<<<200, TB>>>(out, hg + DIM);         // hg[256:512]
}

// round 4
// speedup vs baseline: 1.8983x; 1.3494x over previous
#include <cuda_runtime.h>
#include <cuda_bf16.h>
#include <cstdint>

#define N_NODES 50000
#define N_EDGES 800000
#define DIM     256
#define DIM4    64
#define M_TILE  128
#define GRID_M  ((N_NODES + M_TILE - 1) / M_TILE)   // 391

// ---------------- scratch (device globals: allocation-free rule) ----------
__device__ int   g_idx64;
__device__ int   g_deg_out[N_NODES];
__device__ int   g_deg_in [N_NODES];
__device__ float g_norm_s[N_NODES];
__device__ float g_norm_d[N_NODES];
__device__ int   g_row_off[N_NODES + 1];
__device__ int   g_cursor [N_NODES];
__device__ int   g_csr_src[N_EDGES];
// A operand (agg * norm_d) as bf16 hi/lo split, row-major [N_NODES, DIM]
__device__ __align__(16) unsigned short g_ahi[(size_t)N_NODES * DIM];
__device__ __align__(16) unsigned short g_alo[(size_t)N_NODES * DIM];
// W^T bf16 hi/lo splits: WT[n*DIM + k] = W[k*DIM + n]  (col-major B for mma)
__device__ __align__(16) unsigned short g_w0hi[DIM * DIM];
__device__ __align__(16) unsigned short g_w0lo[DIM * DIM];
__device__ __align__(16) unsigned short g_w1hi[DIM * DIM];
__device__ __align__(16) unsigned short g_w1lo[DIM * DIM];
__device__ float g_h1[(size_t)N_NODES * DIM];

// ---------------- index dtype sniffing ------------------------------------
__global__ void detect_kernel(const int* __restrict__ src_w) {
    __shared__ int any;
    if (threadIdx.x == 0) any = 0;
    __syncthreads();
    for (int i = threadIdx.x; i < 4096; i += blockDim.x)
        if (src_w[2 * i + 1] != 0) any = 1;
    __syncthreads();
    if (threadIdx.x == 0) g_idx64 = (any == 0) ? 1 : 0;
}
__device__ __forceinline__ int load_idx(const void* p, int i, int is64) {
    return is64 ? (int)((const long long*)p)[i] : ((const int*)p)[i];
}

// ---------------- degrees, norms, CSR --------------------------------------
__global__ void zero_deg_kernel() {
    int i = blockIdx.x * blockDim.x + threadIdx.x;
    if (i < N_NODES) { g_deg_out[i] = 0; g_deg_in[i] = 0; }
}
__global__ void degree_kernel(const void* __restrict__ src,
                              const void* __restrict__ dst) {
    int e = blockIdx.x * blockDim.x + threadIdx.x;
    if (e >= N_EDGES) return;
    int is64 = g_idx64;
    atomicAdd(&g_deg_out[load_idx(src, e, is64)], 1);
    atomicAdd(&g_deg_in [load_idx(dst, e, is64)], 1);
}
__global__ void norm_kernel() {
    int i = blockIdx.x * blockDim.x + threadIdx.x;
    if (i >= N_NODES) return;
    g_norm_s[i] = rsqrtf(fmaxf((float)g_deg_out[i], 1.f));
    g_norm_d[i] = rsqrtf(fmaxf((float)g_deg_in[i],  1.f));
}
__global__ void scan_kernel() {
    __shared__ int sh[1024];
    __shared__ int carry_s;
    if (threadIdx.x == 0) carry_s = 0;
    __syncthreads();
    for (int base = 0; base < N_NODES; base += 1024) {
        int i = base + (int)threadIdx.x;
        int v = (i < N_NODES) ? g_deg_in[i] : 0;
        sh[threadIdx.x] = v;
        __syncthreads();
        for (int off = 1; off < 1024; off <<= 1) {
            int t = (threadIdx.x >= off) ? sh[threadIdx.x - off] : 0;
            __syncthreads();
            sh[threadIdx.x] += t;
            __syncthreads();
        }
        int incl = sh[threadIdx.x];
        int carry = carry_s;
        if (i < N_NODES) {
            int o = carry + incl - v;
            g_row_off[i] = o;
            g_cursor[i]  = o;
        }
        __syncthreads();
        if (threadIdx.x == 1023) carry_s = carry + incl;
        __syncthreads();
    }
    if (threadIdx.x == 0) g_row_off[N_NODES] = carry_s;
}
__global__ void fill_kernel(const void* __restrict__ src,
                            const void* __restrict__ dst) {
    int e = blockIdx.x * blockDim.x + threadIdx.x;
    if (e >= N_EDGES) return;
    int is64 = g_idx64;
    int s = load_idx(src, e, is64);
    int d = load_idx(dst, e, is64);
    int pos = atomicAdd(&g_cursor[d], 1);
    g_csr_src[pos] = s;
}

// ---------------- weight split: WT_hi/lo[n*DIM+k] = split(W[k*DIM+n]) -------
__global__ void split_w_kernel(const float* __restrict__ W,
                               unsigned short* __restrict__ hiT,
                               unsigned short* __restrict__ loT) {
    int k = blockIdx.x, n = threadIdx.x;
    float x = W[k * DIM + n];
    __nv_bfloat16 h = __float2bfloat16_rn(x);
    float r = x - __bfloat162float(h);
    __nv_bfloat16 l = __float2bfloat16_rn(r);
    hiT[n * DIM + k] = __bfloat16_as_ushort(h);
    loT[n * DIM + k] = __bfloat16_as_ushort(l);
}

// ---------------- aggregation: gather + norm_d + bf16 split ------------------
__global__ __launch_bounds__(256)
void gather_kernel(const float4* __restrict__ h) {
    int warp = (int)((blockIdx.x * blockDim.x + threadIdx.x) >> 5);
    int lane = threadIdx.x & 31;
    int d    = warp >> 1;
    if (d >= N_NODES) return;
    int chunk = ((warp & 1) << 5) + lane;             // float4 index 0..63
    int beg = g_row_off[d];
    int end = g_row_off[d + 1];
    float4 acc = make_float4(0.f, 0.f, 0.f, 0.f);
    for (int j = beg; j < end; j++) {
        int   s  = g_csr_src[j];
        float ns = g_norm_s[s];
        float4 v = h[(size_t)s * DIM4 + chunk];
        acc.x += v.x * ns; acc.y += v.y * ns;
        acc.z += v.z * ns; acc.w += v.w * ns;
    }
    float nd = g_norm_d[d];
    acc.x *= nd; acc.y *= nd; acc.z *= nd; acc.w *= nd;

    float vals[4] = {acc.x, acc.y, acc.z, acc.w};
    unsigned short hs[4], ls[4];
#pragma unroll
    for (int i = 0; i < 4; i++) {
        __nv_bfloat16 hb = __float2bfloat16_rn(vals[i]);
        float r = vals[i] - __bfloat162float(hb);
        __nv_bfloat16 lb = __float2bfloat16_rn(r);
        hs[i] = __bfloat16_as_ushort(hb);
        ls[i] = __bfloat16_as_ushort(lb);
    }
    size_t off = (size_t)d * DIM + chunk * 4;
    *(uint2*)&g_ahi[off] = make_uint2(((uint32_t)hs[1] << 16) | hs[0],
                                      ((uint32_t)hs[3] << 16) | hs[2]);
    *(uint2*)&g_alo[off] = make_uint2(((uint32_t)ls[1] << 16) | ls[0],
                                      ((uint32_t)ls[3] << 16) | ls[2]);
}

// ---------------- mma.sync GEMM: out = prelu(A @ W + b) ---------------------
// A [M,256] bf16 hi/lo, B = WT [n][k] bf16 hi/lo (col-major B).
// D = Ahi@Bhi + Ahi@Blo + Alo@Bhi, fp32 accum via m16n8k16 HMMA.
// SMEM pitch: 24 bf16 (48B) per row -> fragment LDS pattern is conflict-free.
#define PITCH   24
#define SA_SZ   (128 * PITCH * 2)            // 6144 B per buffer
#define SB_SZ   (256 * PITCH * 2)            // 12288 B per buffer
#define SM_AHI(b) ((b) * SA_SZ)
#define SM_ALO(b) (2 * SA_SZ + (b) * SA_SZ)
#define SM_BHI(b) (4 * SA_SZ + (b) * SB_SZ)
#define SM_BLO(b) (4 * SA_SZ + 2 * SB_SZ + (b) * SB_SZ)
#define SM_TOTAL  (4 * SA_SZ + 4 * SB_SZ)    // 73728 B

__device__ __forceinline__ void mma16816(float* c, const uint32_t* a,
                                         uint32_t b0, uint32_t b1) {
    asm volatile(
        "mma.sync.aligned.m16n8k16.row.col.f32.bf16.bf16.f32 "
        "{%0,%1,%2,%3}, {%4,%5,%6,%7}, {%8,%9}, {%0,%1,%2,%3};"
        : "+f"(c[0]), "+f"(c[1]), "+f"(c[2]), "+f"(c[3])
        : "r"(a[0]), "r"(a[1]), "r"(a[2]), "r"(a[3]), "r"(b0), "r"(b1));
}

__global__ __launch_bounds__(256, 1)
void gemm_mma_kernel(const unsigned short* __restrict__ Ahi,
                     const unsigned short* __restrict__ Alo,
                     const unsigned short* __restrict__ Bhi,
                     const unsigned short* __restrict__ Blo,
                     const float* __restrict__ bias,
                     const float* __restrict__ prelu_a,
                     float* __restrict__ out, int M) {
    extern __shared__ char smem[];
    const int tid  = threadIdx.x;
    const int wid  = tid >> 5;
    const int lane = tid & 31;
    const int bm   = blockIdx.x * M_TILE;
    const int wm   = (wid >> 1) * 32;        // warp M offset (0,32,64,96)
    const int wn   = (wid & 1) * 128;        // warp N offset (0,128)
    const int qrow = lane >> 2;              // T/4
    const int qcol = lane & 3;               // T%4

    // A loader coords: row = tid>>1, half = tid&1 (8 bf16 = 16B each)
    const int a_row  = tid >> 1;
    const int a_half = tid & 1;
    const int a_gr   = bm + a_row;

    float c[2][16][4];
#pragma unroll
    for (int mt = 0; mt < 2; mt++)
#pragma unroll
        for (int nt = 0; nt < 16; nt++)
#pragma unroll
            for (int i = 0; i < 4; i++) c[mt][nt][i] = 0.f;

    uint4 pAh, pAl, pB0h, pB1h, pB0l, pB1l;

    // ---- prefetch k-step 0 ----
    {
        pAh = make_uint4(0, 0, 0, 0); pAl = pAh;
        if (a_gr < M) {
            pAh = *(const uint4*)(Ahi + (size_t)a_gr * DIM + a_half * 8);
            pAl = *(const uint4*)(Alo + (size_t)a_gr * DIM + a_half * 8);
        }
        const uint4* pbh = (const uint4*)(Bhi + (size_t)tid * DIM);
        const uint4* pbl = (const uint4*)(Blo + (size_t)tid * DIM);
        pB0h = pbh[0]; pB1h = pbh[1];
        pB0l = pbl[0]; pB1l = pbl[1];
    }
    // store k-step 0 into buffer 0
    *(uint4*)(smem + SM_AHI(0) + a_row * 48 + a_half * 16) = pAh;
    *(uint4*)(smem + SM_ALO(0) + a_row * 48 + a_half * 16) = pAl;
    *(uint4*)(smem + SM_BHI(0) + tid * 48)      = pB0h;
    *(uint4*)(smem + SM_BHI(0) + tid * 48 + 16) = pB1h;
    *(uint4*)(smem + SM_BLO(0) + tid * 48)      = pB0l;
    *(uint4*)(smem + SM_BLO(0) + tid * 48 + 16) = pB1l;
    __syncthreads();

    for (int ks = 0; ks < 16; ks++) {
        const int buf = ks & 1;
        // ---- prefetch next k-step into registers ----
        if (ks < 15) {
            int k0 = (ks + 1) * 16;
            pAh = make_uint4(0, 0, 0, 0); pAl = pAh;
            if (a_gr < M) {
                pAh = *(const uint4*)(Ahi + (size_t)a_gr * DIM + k0 + a_half * 8);
                pAl = *(const uint4*)(Alo + (size_t)a_gr * DIM + k0 + a_half * 8);
            }
            const uint4* pbh = (const uint4*)(Bhi + (size_t)tid * DIM + k0);
            const uint4* pbl = (const uint4*)(Blo + (size_t)tid * DIM + k0);
            pB0h = pbh[0]; pB1h = pbh[1];
            pB0l = pbl[0]; pB1l = pbl[1];
        }
        // ---- compute on current buffer ----
        uint32_t ah[2][4], al[2][4];
#pragma unroll
        for (int mt = 0; mt < 2; mt++) {
            int base = (wm + mt * 16 + qrow) * 48 + qcol * 4;
            ah[mt][0] = *(const uint32_t*)(smem + SM_AHI(buf) + base);
            ah[mt][1] = *(const uint32_t*)(smem + SM_AHI(buf) + base + 8 * 48);
            ah[mt][2] = *(const uint32_t*)(smem + SM_AHI(buf) + base + 16);
            ah[mt][3] = *(const uint32_t*)(smem + SM_AHI(buf) + base + 8 * 48 + 16);
            al[mt][0] = *(const uint32_t*)(smem + SM_ALO(buf) + base);
            al[mt][1] = *(const uint32_t*)(smem + SM_ALO(buf) + base + 8 * 48);
            al[mt][2] = *(const uint32_t*)(smem + SM_ALO(buf) + base + 16);
            al[mt][3] = *(const uint32_t*)(smem + SM_ALO(buf) + base + 8 * 48 + 16);
        }
#pragma unroll
        for (int nt = 0; nt < 16; nt++) {
            int bb = (wn + nt * 8 + qrow) * 48 + qcol * 4;
            uint32_t bh0 = *(const uint32_t*)(smem + SM_BHI(buf) + bb);
            uint32_t bh1 = *(const uint32_t*)(smem + SM_BHI(buf) + bb + 16);
            uint32_t bl0 = *(const uint32_t*)(smem + SM_BLO(buf) + bb);
            uint32_t bl1 = *(const uint32_t*)(smem + SM_BLO(buf) + bb + 16);
#pragma unroll
            for (int mt = 0; mt < 2; mt++) {
                mma16816(c[mt][nt], ah[mt], bh0, bh1);
                mma16816(c[mt][nt], ah[mt], bl0, bl1);
                mma16816(c[mt][nt], al[mt], bh0, bh1);
            }
        }
        // ---- store prefetched tile into other buffer ----
        if (ks < 15) {
            int nb = buf ^ 1;
            *(uint4*)(smem + SM_AHI(nb) + a_row * 48 + a_half * 16) = pAh;
            *(uint4*)(smem + SM_ALO(nb) + a_row * 48 + a_half * 16) = pAl;
            *(uint4*)(smem + SM_BHI(nb) + tid * 48)      = pB0h;
            *(uint4*)(smem + SM_BHI(nb) + tid * 48 + 16) = pB1h;
            *(uint4*)(smem + SM_BLO(nb) + tid * 48)      = pB0l;
            *(uint4*)(smem + SM_BLO(nb) + tid * 48 + 16) = pB1l;
        }
        __syncthreads();
    }

    // ---- epilogue: bias + PReLU, direct float2 stores ----
    const float pa = __ldg(prelu_a);
#pragma unroll
    for (int nt = 0; nt < 16; nt++) {
        int col = wn + nt * 8 + qcol * 2;
        float bx = bias[col], by = bias[col + 1];
#pragma unroll
        for (int mt = 0; mt < 2; mt++) {
            int r0 = bm + wm + mt * 16 + qrow;
            float v0 = c[mt][nt][0] + bx;
            float v1 = c[mt][nt][1] + by;
            float v2 = c[mt][nt][2] + bx;
            float v3 = c[mt][nt][3] + by;
            v0 = (v0 >= 0.f) ? v0 : pa * v0;
            v1 = (v1 >= 0.f) ? v1 : pa * v1;
            v2 = (v2 >= 0.f) ? v2 : pa * v2;
            v3 = (v3 >= 0.f) ? v3 : pa * v3;
            if (r0 < M)
                *(float2*)(out + (size_t)r0 * DIM + col) = make_float2(v0, v1);
            if (r0 + 8 < M)
                *(float2*)(out + (size_t)(r0 + 8) * DIM + col) = make_float2(v2, v3);
        }
    }
}

// ---------------- readout ---------------------------------------------------
__global__ void zero_hg_kernel(float* __restrict__ hg) {
    int i = blockIdx.x * blockDim.x + threadIdx.x;
    if (i < 2 * DIM) hg[i] = 0.f;
}
__global__ void colsum_kernel(const float* __restrict__ h,
                              float* __restrict__ hg) {
    int c = threadIdx.x;
    int r0 = blockIdx.x * 250;
    float s = 0.f;
    for (int r = 0; r < 250; r++)
        s += h[(size_t)(r0 + r) * DIM + c];
    atomicAdd(&hg[c], s);
}

// ---------------- launch ----------------------------------------------------
extern "C" void kernel_launch(void* const* d_in, const int* in_sizes, int n_in,
                              void* d_out, int out_size) {
    const float* feat = (const float*)d_in[0];
    const void*  src  = d_in[1];
    const void*  dst  = d_in[2];
    const float* W0   = (const float*)d_in[3];
    const float* b0   = (const float*)d_in[4];
    const float* W1   = (const float*)d_in[5];
    const float* b1   = (const float*)d_in[6];
    const float* pa   = (const float*)d_in[7];
    float* out = (float*)d_out;
    float* hg  = out + (size_t)N_NODES * DIM;

    void *p_ahi, *p_alo, *p_w0hi, *p_w0lo, *p_w1hi, *p_w1lo, *p_h1;
    cudaGetSymbolAddress(&p_ahi,  g_ahi);
    cudaGetSymbolAddress(&p_alo,  g_alo);
    cudaGetSymbolAddress(&p_w0hi, g_w0hi);
    cudaGetSymbolAddress(&p_w0lo, g_w0lo);
    cudaGetSymbolAddress(&p_w1hi, g_w1hi);
    cudaGetSymbolAddress(&p_w1lo, g_w1lo);
    cudaGetSymbolAddress(&p_h1,   g_h1);

    cudaFuncSetAttribute(gemm_mma_kernel,
                         cudaFuncAttributeMaxDynamicSharedMemorySize, SM_TOTAL);

    const int TB = 256;
    const int nodeBlk = (N_NODES + TB - 1) / TB;
    const int edgeBlk = (N_EDGES + TB - 1) / TB;
    const int gatherBlk = (N_NODES * 2 * 32 + TB - 1) / TB;

    // ---- preprocessing: degrees, norms, CSR, weight splits ----
    detect_kernel<<<1, 256>>>((const int*)src);
    zero_deg_kernel<<<nodeBlk, TB>>>();
    degree_kernel<<<edgeBlk, TB>>>(src, dst);
    norm_kernel<<<nodeBlk, TB>>>();
    scan_kernel<<<1, 1024>>>();
    fill_kernel<<<edgeBlk, TB>>>(src, dst);
    split_w_kernel<<<DIM, DIM>>>(W0, (unsigned short*)p_w0hi, (unsigned short*)p_w0lo);
    split_w_kernel<<<DIM, DIM>>>(W1, (unsigned short*)p_w1hi, (unsigned short*)p_w1lo);
    zero_hg_kernel<<<2, TB>>>(hg);

    // ---- layer 1 ----
    gather_kernel<<<gatherBlk, TB>>>((const float4*)feat);
    gemm_mma_kernel<<<GRID_M, TB, SM_TOTAL>>>(
        (const unsigned short*)p_ahi, (const unsigned short*)p_alo,
        (const unsigned short*)p_w0hi, (const unsigned short*)p_w0lo,
        b0, pa, (float*)p_h1, N_NODES);
    colsum_kernel<<<200, TB>>>((const float*)p_h1, hg);

    // ---- layer 2 ----
    gather_kernel<<<gatherBlk, TB>>>((const float4*)p_h1);
    gemm_mma_kernel<<<GRID_M, TB, SM_TOTAL>>>(
        (const unsigned short*)p_ahi, (const unsigned short*)p_alo,
        (const unsigned short*)p_w1hi, (const unsigned short*)p_w1lo,
        b1, pa, out, N_NODES);
    colsum_kernel<<<200, TB>>>(out, hg + DIM);
}

// round 5
// speedup vs baseline: 2.1786x; 1.1477x over previous
#include <cuda_runtime.h>
#include <cuda_bf16.h>
#include <cstdint>

#define N_NODES 50000
#define N_EDGES 800000
#define DIM     256
#define DIM4    64
#define M_TILE  128
#define GRID_M  ((N_NODES + M_TILE - 1) / M_TILE)   // 391
#define SCAN_NB ((N_NODES + 1023) / 1024)           // 49

// ---------------- scratch (device globals: allocation-free rule) ----------
__device__ int   g_idx64;
__device__ int   g_deg_out[N_NODES];
__device__ int   g_deg_in [N_NODES];
__device__ float g_norm_s[N_NODES];
__device__ float g_norm_d[N_NODES];
__device__ int   g_row_off[N_NODES + 1];
__device__ int   g_cursor [N_NODES];
__device__ int   g_incl   [N_NODES];
__device__ int   g_bsum[64];
__device__ int   g_boff[64];
__device__ int   g_csr_src[N_EDGES];
__device__ float g_csr_w  [N_EDGES];     // norm_s[src] per CSR slot
// A operand (agg * norm_d) as bf16 hi/lo split, row-major [N_NODES, DIM]
__device__ __align__(16) unsigned short g_ahi[(size_t)N_NODES * DIM];
__device__ __align__(16) unsigned short g_alo[(size_t)N_NODES * DIM];
// W^T bf16 hi/lo splits: WT[n*DIM + k] = W[k*DIM + n]  (col-major B for mma)
__device__ __align__(16) unsigned short g_w0hi[DIM * DIM];
__device__ __align__(16) unsigned short g_w0lo[DIM * DIM];
__device__ __align__(16) unsigned short g_w1hi[DIM * DIM];
__device__ __align__(16) unsigned short g_w1lo[DIM * DIM];
__device__ float g_h1[(size_t)N_NODES * DIM];

// ---------------- index dtype sniffing ------------------------------------
__global__ void detect_kernel(const int* __restrict__ src_w) {
    __shared__ int any;
    if (threadIdx.x == 0) any = 0;
    __syncthreads();
    for (int i = threadIdx.x; i < 4096; i += blockDim.x)
        if (src_w[2 * i + 1] != 0) any = 1;
    __syncthreads();
    if (threadIdx.x == 0) g_idx64 = (any == 0) ? 1 : 0;
}
__device__ __forceinline__ int load_idx(const void* p, int i, int is64) {
    return is64 ? (int)((const long long*)p)[i] : ((const int*)p)[i];
}

// ---------------- degrees, norms -------------------------------------------
__global__ void zero_deg_kernel() {
    int i = blockIdx.x * blockDim.x + threadIdx.x;
    if (i < N_NODES) { g_deg_out[i] = 0; g_deg_in[i] = 0; }
}
__global__ void degree_kernel(const void* __restrict__ src,
                              const void* __restrict__ dst) {
    int e = blockIdx.x * blockDim.x + threadIdx.x;
    if (e >= N_EDGES) return;
    int is64 = g_idx64;
    atomicAdd(&g_deg_out[load_idx(src, e, is64)], 1);
    atomicAdd(&g_deg_in [load_idx(dst, e, is64)], 1);
}
__global__ void norm_kernel() {
    int i = blockIdx.x * blockDim.x + threadIdx.x;
    if (i >= N_NODES) return;
    g_norm_s[i] = rsqrtf(fmaxf((float)g_deg_out[i], 1.f));
    g_norm_d[i] = rsqrtf(fmaxf((float)g_deg_in[i],  1.f));
}

// ---------------- parallel scan (3 small kernels) ---------------------------
__global__ void scan_blocks_kernel() {
    __shared__ int sh[1024];
    int i = blockIdx.x * 1024 + threadIdx.x;
    int v = (i < N_NODES) ? g_deg_in[i] : 0;
    sh[threadIdx.x] = v;
    __syncthreads();
    for (int off = 1; off < 1024; off <<= 1) {
        int t = (threadIdx.x >= off) ? sh[threadIdx.x - off] : 0;
        __syncthreads();
        sh[threadIdx.x] += t;
        __syncthreads();
    }
    if (i < N_NODES) g_incl[i] = sh[threadIdx.x];
    if (threadIdx.x == 1023) g_bsum[blockIdx.x] = sh[1023];
}
__global__ void scan_bsums_kernel() {     // 1 block, 64 threads
    __shared__ int sh[64];
    int v = (threadIdx.x < SCAN_NB) ? g_bsum[threadIdx.x] : 0;
    sh[threadIdx.x] = v;
    __syncthreads();
    for (int off = 1; off < 64; off <<= 1) {
        int t = (threadIdx.x >= off) ? sh[threadIdx.x - off] : 0;
        __syncthreads();
        sh[threadIdx.x] += t;
        __syncthreads();
    }
    if (threadIdx.x < SCAN_NB) g_boff[threadIdx.x] = sh[threadIdx.x] - v;
}
__global__ void scan_finalize_kernel() {
    int i = blockIdx.x * blockDim.x + threadIdx.x;
    if (i >= N_NODES) return;
    int o = g_boff[i >> 10] + g_incl[i] - g_deg_in[i];
    g_row_off[i] = o;
    g_cursor[i]  = o;
    if (i == 0) g_row_off[N_NODES] = N_EDGES;
}

// fill CSR: slot gets (src, norm_s[src])
__global__ void fill_kernel(const void* __restrict__ src,
                            const void* __restrict__ dst) {
    int e = blockIdx.x * blockDim.x + threadIdx.x;
    if (e >= N_EDGES) return;
    int is64 = g_idx64;
    int s = load_idx(src, e, is64);
    int d = load_idx(dst, e, is64);
    int pos = atomicAdd(&g_cursor[d], 1);
    g_csr_src[pos] = s;
    g_csr_w[pos]   = g_norm_s[s];
}

// ---------------- weight split: WT_hi/lo[n*DIM+k] = split(W[k*DIM+n]) -------
__global__ void split_w_kernel(const float* __restrict__ W,
                               unsigned short* __restrict__ hiT,
                               unsigned short* __restrict__ loT) {
    int k = blockIdx.x, n = threadIdx.x;
    float x = W[k * DIM + n];
    __nv_bfloat16 h = __float2bfloat16_rn(x);
    float r = x - __bfloat162float(h);
    __nv_bfloat16 l = __float2bfloat16_rn(r);
    hiT[n * DIM + k] = __bfloat16_as_ushort(h);
    loT[n * DIM + k] = __bfloat16_as_ushort(l);
}

// ---------------- aggregation: 1 warp/node, unroll-2, fused split -----------
// agg[d] = norm_d[d] * sum_j w_j * h[src_j]; lane owns chunks lane, lane+32.
__device__ __forceinline__ void fma4(float4& a, float w, const float4& v) {
    a.x += w * v.x; a.y += w * v.y; a.z += w * v.z; a.w += w * v.w;
}
__device__ __forceinline__ void split_store(float4 acc, size_t off) {
    unsigned short hs[4], ls[4];
    float vals[4] = {acc.x, acc.y, acc.z, acc.w};
#pragma unroll
    for (int i = 0; i < 4; i++) {
        __nv_bfloat16 hb = __float2bfloat16_rn(vals[i]);
        float r = vals[i] - __bfloat162float(hb);
        __nv_bfloat16 lb = __float2bfloat16_rn(r);
        hs[i] = __bfloat16_as_ushort(hb);
        ls[i] = __bfloat16_as_ushort(lb);
    }
    *(uint2*)&g_ahi[off] = make_uint2(((uint32_t)hs[1] << 16) | hs[0],
                                      ((uint32_t)hs[3] << 16) | hs[2]);
    *(uint2*)&g_alo[off] = make_uint2(((uint32_t)ls[1] << 16) | ls[0],
                                      ((uint32_t)ls[3] << 16) | ls[2]);
}

__global__ __launch_bounds__(256)
void gather_kernel(const float4* __restrict__ h) {
    int d    = (int)((blockIdx.x * blockDim.x + threadIdx.x) >> 5);
    int lane = threadIdx.x & 31;
    if (d >= N_NODES) return;
    int beg = g_row_off[d];
    int end = g_row_off[d + 1];
    float4 acc0 = make_float4(0.f, 0.f, 0.f, 0.f);
    float4 acc1 = make_float4(0.f, 0.f, 0.f, 0.f);
    int j = beg;
    for (; j + 1 < end; j += 2) {
        int   s0 = g_csr_src[j],   s1 = g_csr_src[j + 1];
        float w0 = g_csr_w[j],     w1 = g_csr_w[j + 1];
        const float4* r0 = h + (size_t)s0 * DIM4;
        const float4* r1 = h + (size_t)s1 * DIM4;
        float4 a0 = r0[lane];
        float4 a1 = r1[lane];
        float4 b0 = r0[lane + 32];
        float4 b1 = r1[lane + 32];
        fma4(acc0, w0, a0); fma4(acc0, w1, a1);
        fma4(acc1, w0, b0); fma4(acc1, w1, b1);
    }
    if (j < end) {
        int   s0 = g_csr_src[j];
        float w0 = g_csr_w[j];
        const float4* r0 = h + (size_t)s0 * DIM4;
        fma4(acc0, w0, r0[lane]);
        fma4(acc1, w0, r0[lane + 32]);
    }
    float nd = g_norm_d[d];
    acc0.x *= nd; acc0.y *= nd; acc0.z *= nd; acc0.w *= nd;
    acc1.x *= nd; acc1.y *= nd; acc1.z *= nd; acc1.w *= nd;
    split_store(acc0, (size_t)d * DIM + lane * 4);
    split_store(acc1, (size_t)d * DIM + (lane + 32) * 4);
}

// ---------------- mma.sync GEMM: out = prelu(A @ W + b) ---------------------
#define PITCH   24
#define SA_SZ   (128 * PITCH * 2)            // 6144 B per buffer
#define SB_SZ   (256 * PITCH * 2)            // 12288 B per buffer
#define SM_AHI(b) ((b) * SA_SZ)
#define SM_ALO(b) (2 * SA_SZ + (b) * SA_SZ)
#define SM_BHI(b) (4 * SA_SZ + (b) * SB_SZ)
#define SM_BLO(b) (4 * SA_SZ + 2 * SB_SZ + (b) * SB_SZ)
#define SM_TOTAL  (4 * SA_SZ + 4 * SB_SZ)    // 73728 B

__device__ __forceinline__ void mma16816(float* c, const uint32_t* a,
                                         uint32_t b0, uint32_t b1) {
    asm volatile(
        "mma.sync.aligned.m16n8k16.row.col.f32.bf16.bf16.f32 "
        "{%0,%1,%2,%3}, {%4,%5,%6,%7}, {%8,%9}, {%0,%1,%2,%3};"
        : "+f"(c[0]), "+f"(c[1]), "+f"(c[2]), "+f"(c[3])
        : "r"(a[0]), "r"(a[1]), "r"(a[2]), "r"(a[3]), "r"(b0), "r"(b1));
}

__global__ __launch_bounds__(256, 1)
void gemm_mma_kernel(const unsigned short* __restrict__ Ahi,
                     const unsigned short* __restrict__ Alo,
                     const unsigned short* __restrict__ Bhi,
                     const unsigned short* __restrict__ Blo,
                     const float* __restrict__ bias,
                     const float* __restrict__ prelu_a,
                     float* __restrict__ out, int M) {
    extern __shared__ char smem[];
    const int tid  = threadIdx.x;
    const int wid  = tid >> 5;
    const int lane = tid & 31;
    const int bm   = blockIdx.x * M_TILE;
    const int wm   = (wid >> 1) * 32;
    const int wn   = (wid & 1) * 128;
    const int qrow = lane >> 2;
    const int qcol = lane & 3;

    const int a_row  = tid >> 1;
    const int a_half = tid & 1;
    const int a_gr   = bm + a_row;

    float c[2][16][4];
#pragma unroll
    for (int mt = 0; mt < 2; mt++)
#pragma unroll
        for (int nt = 0; nt < 16; nt++)
#pragma unroll
            for (int i = 0; i < 4; i++) c[mt][nt][i] = 0.f;

    uint4 pAh, pAl, pB0h, pB1h, pB0l, pB1l;

    {
        pAh = make_uint4(0, 0, 0, 0); pAl = pAh;
        if (a_gr < M) {
            pAh = *(const uint4*)(Ahi + (size_t)a_gr * DIM + a_half * 8);
            pAl = *(const uint4*)(Alo + (size_t)a_gr * DIM + a_half * 8);
        }
        const uint4* pbh = (const uint4*)(Bhi + (size_t)tid * DIM);
        const uint4* pbl = (const uint4*)(Blo + (size_t)tid * DIM);
        pB0h = pbh[0]; pB1h = pbh[1];
        pB0l = pbl[0]; pB1l = pbl[1];
    }
    *(uint4*)(smem + SM_AHI(0) + a_row * 48 + a_half * 16) = pAh;
    *(uint4*)(smem + SM_ALO(0) + a_row * 48 + a_half * 16) = pAl;
    *(uint4*)(smem + SM_BHI(0) + tid * 48)      = pB0h;
    *(uint4*)(smem + SM_BHI(0) + tid * 48 + 16) = pB1h;
    *(uint4*)(smem + SM_BLO(0) + tid * 48)      = pB0l;
    *(uint4*)(smem + SM_BLO(0) + tid * 48 + 16) = pB1l;
    __syncthreads();

    for (int ks = 0; ks < 16; ks++) {
        const int buf = ks & 1;
        if (ks < 15) {
            int k0 = (ks + 1) * 16;
            pAh = make_uint4(0, 0, 0, 0); pAl = pAh;
            if (a_gr < M) {
                pAh = *(const uint4*)(Ahi + (size_t)a_gr * DIM + k0 + a_half * 8);
                pAl = *(const uint4*)(Alo + (size_t)a_gr * DIM + k0 + a_half * 8);
            }
            const uint4* pbh = (const uint4*)(Bhi + (size_t)tid * DIM + k0);
            const uint4* pbl = (const uint4*)(Blo + (size_t)tid * DIM + k0);
            pB0h = pbh[0]; pB1h = pbh[1];
            pB0l = pbl[0]; pB1l = pbl[1];
        }
        uint32_t ah[2][4], al[2][4];
#pragma unroll
        for (int mt = 0; mt < 2; mt++) {
            int base = (wm + mt * 16 + qrow) * 48 + qcol * 4;
            ah[mt][0] = *(const uint32_t*)(smem + SM_AHI(buf) + base);
            ah[mt][1] = *(const uint32_t*)(smem + SM_AHI(buf) + base + 8 * 48);
            ah[mt][2] = *(const uint32_t*)(smem + SM_AHI(buf) + base + 16);
            ah[mt][3] = *(const uint32_t*)(smem + SM_AHI(buf) + base + 8 * 48 + 16);
            al[mt][0] = *(const uint32_t*)(smem + SM_ALO(buf) + base);
            al[mt][1] = *(const uint32_t*)(smem + SM_ALO(buf) + base + 8 * 48);
            al[mt][2] = *(const uint32_t*)(smem + SM_ALO(buf) + base + 16);
            al[mt][3] = *(const uint32_t*)(smem + SM_ALO(buf) + base + 8 * 48 + 16);
        }
#pragma unroll
        for (int nt = 0; nt < 16; nt++) {
            int bb = (wn + nt * 8 + qrow) * 48 + qcol * 4;
            uint32_t bh0 = *(const uint32_t*)(smem + SM_BHI(buf) + bb);
            uint32_t bh1 = *(const uint32_t*)(smem + SM_BHI(buf) + bb + 16);
            uint32_t bl0 = *(const uint32_t*)(smem + SM_BLO(buf) + bb);
            uint32_t bl1 = *(const uint32_t*)(smem + SM_BLO(buf) + bb + 16);
#pragma unroll
            for (int mt = 0; mt < 2; mt++) {
                mma16816(c[mt][nt], ah[mt], bh0, bh1);
                mma16816(c[mt][nt], ah[mt], bl0, bl1);
                mma16816(c[mt][nt], al[mt], bh0, bh1);
            }
        }
        if (ks < 15) {
            int nb = buf ^ 1;
            *(uint4*)(smem + SM_AHI(nb) + a_row * 48 + a_half * 16) = pAh;
            *(uint4*)(smem + SM_ALO(nb) + a_row * 48 + a_half * 16) = pAl;
            *(uint4*)(smem + SM_BHI(nb) + tid * 48)      = pB0h;
            *(uint4*)(smem + SM_BHI(nb) + tid * 48 + 16) = pB1h;
            *(uint4*)(smem + SM_BLO(nb) + tid * 48)      = pB0l;
            *(uint4*)(smem + SM_BLO(nb) + tid * 48 + 16) = pB1l;
        }
        __syncthreads();
    }

    const float pa = __ldg(prelu_a);
#pragma unroll
    for (int nt = 0; nt < 16; nt++) {
        int col = wn + nt * 8 + qcol * 2;
        float bx = bias[col], by = bias[col + 1];
#pragma unroll
        for (int mt = 0; mt < 2; mt++) {
            int r0 = bm + wm + mt * 16 + qrow;
            float v0 = c[mt][nt][0] + bx;
            float v1 = c[mt][nt][1] + by;
            float v2 = c[mt][nt][2] + bx;
            float v3 = c[mt][nt][3] + by;
            v0 = (v0 >= 0.f) ? v0 : pa * v0;
            v1 = (v1 >= 0.f) ? v1 : pa * v1;
            v2 = (v2 >= 0.f) ? v2 : pa * v2;
            v3 = (v3 >= 0.f) ? v3 : pa * v3;
            if (r0 < M)
                *(float2*)(out + (size_t)r0 * DIM + col) = make_float2(v0, v1);
            if (r0 + 8 < M)
                *(float2*)(out + (size_t)(r0 + 8) * DIM + col) = make_float2(v2, v3);
        }
    }
}

// ---------------- readout ---------------------------------------------------
__global__ void zero_hg_kernel(float* __restrict__ hg) {
    int i = blockIdx.x * blockDim.x + threadIdx.x;
    if (i < 2 * DIM) hg[i] = 0.f;
}
__global__ void colsum_kernel(const float* __restrict__ h,
                              float* __restrict__ hg) {
    int c = threadIdx.x;
    int r0 = blockIdx.x * 250;
    float s = 0.f;
    for (int r = 0; r < 250; r++)
        s += h[(size_t)(r0 + r) * DIM + c];
    atomicAdd(&hg[c], s);
}

// ---------------- launch ----------------------------------------------------
extern "C" void kernel_launch(void* const* d_in, const int* in_sizes, int n_in,
                              void* d_out, int out_size) {
    const float* feat = (const float*)d_in[0];
    const void*  src  = d_in[1];
    const void*  dst  = d_in[2];
    const float* W0   = (const float*)d_in[3];
    const float* b0   = (const float*)d_in[4];
    const float* W1   = (const float*)d_in[5];
    const float* b1   = (const float*)d_in[6];
    const float* pa   = (const float*)d_in[7];
    float* out = (float*)d_out;
    float* hg  = out + (size_t)N_NODES * DIM;

    void *p_ahi, *p_alo, *p_w0hi, *p_w0lo, *p_w1hi, *p_w1lo, *p_h1;
    cudaGetSymbolAddress(&p_ahi,  g_ahi);
    cudaGetSymbolAddress(&p_alo,  g_alo);
    cudaGetSymbolAddress(&p_w0hi, g_w0hi);
    cudaGetSymbolAddress(&p_w0lo, g_w0lo);
    cudaGetSymbolAddress(&p_w1hi, g_w1hi);
    cudaGetSymbolAddress(&p_w1lo, g_w1lo);
    cudaGetSymbolAddress(&p_h1,   g_h1);

    cudaFuncSetAttribute(gemm_mma_kernel,
                         cudaFuncAttributeMaxDynamicSharedMemorySize, SM_TOTAL);

    const int TB = 256;
    const int nodeBlk = (N_NODES + TB - 1) / TB;
    const int edgeBlk = (N_EDGES + TB - 1) / TB;
    const int gatherBlk = (N_NODES * 32 + TB - 1) / TB;   // 1 warp/node

    // ---- preprocessing: degrees, norms, CSR, weight splits ----
    detect_kernel<<<1, 256>>>((const int*)src);
    zero_deg_kernel<<<nodeBlk, TB>>>();
    degree_kernel<<<edgeBlk, TB>>>(src, dst);
    norm_kernel<<<nodeBlk, TB>>>();
    scan_blocks_kernel<<<SCAN_NB, 1024>>>();
    scan_bsums_kernel<<<1, 64>>>();
    scan_finalize_kernel<<<nodeBlk, TB>>>();
    fill_kernel<<<edgeBlk, TB>>>(src, dst);
    split_w_kernel<<<DIM, DIM>>>(W0, (unsigned short*)p_w0hi, (unsigned short*)p_w0lo);
    split_w_kernel<<<DIM, DIM>>>(W1, (unsigned short*)p_w1hi, (unsigned short*)p_w1lo);
    zero_hg_kernel<<<2, TB>>>(hg);

    // ---- layer 1 ----
    gather_kernel<<<gatherBlk, TB>>>((const float4*)feat);
    gemm_mma_kernel<<<GRID_M, TB, SM_TOTAL>>>(
        (const unsigned short*)p_ahi, (const unsigned short*)p_alo,
        (const unsigned short*)p_w0hi, (const unsigned short*)p_w0lo,
        b0, pa, (float*)p_h1, N_NODES);
    colsum_kernel<<<200, TB>>>((const float*)p_h1, hg);

    // ---- layer 2 ----
    gather_kernel<<<gatherBlk, TB>>>((const float4*)p_h1);
    gemm_mma_kernel<<<GRID_M, TB, SM_TOTAL>>>(
        (const unsigned short*)p_ahi, (const unsigned short*)p_alo,
        (const unsigned short*)p_w1hi, (const unsigned short*)p_w1lo,
        b1, pa, out, N_NODES);
    colsum_kernel<<<200, TB>>>(out, hg + DIM);
}